// round 13
// baseline (speedup 1.0000x reference)
#include <cuda_runtime.h>
#include <cuda_fp16.h>
#include <math.h>
#include <stdint.h>

// ---------------------------------------------------------------------------
// Problem constants
// ---------------------------------------------------------------------------
#define B_TOT   2048
#define L_TOK   49
#define C_DIM   512
#define H_HEADS 16
#define HD_DIM  32
#define ROWS    (B_TOT * L_TOK)        // 100352 = 784 * 128

// Scratch (device globals; allocation-free per harness rules)
static __device__ unsigned short g_xh[(size_t)ROWS * C_DIM];
static __device__ unsigned short g_qkvh[(size_t)ROWS * 3 * C_DIM];
static __device__ unsigned short g_atth[(size_t)ROWS * C_DIM];
static __device__ unsigned short g_wqkvth[3 * C_DIM * C_DIM];
static __device__ unsigned short g_wprojth[C_DIM * C_DIM];
static __device__ float g_bm[64 * 16 * 49 * 56];

// ---------------------------------------------------------------------------
// Helpers
// ---------------------------------------------------------------------------
__device__ __forceinline__ uint32_t smem_u32(const void* p) {
    uint32_t a;
    asm("{ .reg .u64 t; cvta.to.shared.u64 t, %1; cvt.u32.u64 %0, t; }" : "=r"(a) : "l"(p));
    return a;
}

__device__ __forceinline__ void ldsm_x4(uint32_t addr, uint32_t& r0, uint32_t& r1,
                                        uint32_t& r2, uint32_t& r3) {
    asm volatile("ldmatrix.sync.aligned.m8n8.x4.shared.b16 {%0,%1,%2,%3}, [%4];"
                 : "=r"(r0), "=r"(r1), "=r"(r2), "=r"(r3) : "r"(addr));
}

__device__ __forceinline__ void ldsm_x4_t(uint32_t addr, uint32_t& r0, uint32_t& r1,
                                          uint32_t& r2, uint32_t& r3) {
    asm volatile("ldmatrix.sync.aligned.m8n8.x4.trans.shared.b16 {%0,%1,%2,%3}, [%4];"
                 : "=r"(r0), "=r"(r1), "=r"(r2), "=r"(r3) : "r"(addr));
}

__device__ __forceinline__ void cp_async16(uint32_t d, const void* s) {
    asm volatile("cp.async.cg.shared.global [%0], [%1], 16;" :: "r"(d), "l"(s) : "memory");
}
__device__ __forceinline__ void cp_async16z(uint32_t d, const void* s, uint32_t sz) {
    asm volatile("cp.async.cg.shared.global [%0], [%1], 16, %2;"
                 :: "r"(d), "l"(s), "r"(sz) : "memory");
}
#define CP_COMMIT() asm volatile("cp.async.commit_group;" ::: "memory")

#define MMA_F16(c, a0, a1, a2, a3, b0, b1)                                      \
    asm volatile(                                                               \
        "mma.sync.aligned.m16n8k16.row.col.f32.f16.f16.f32 "                    \
        "{%0,%1,%2,%3}, {%4,%5,%6,%7}, {%8,%9}, {%0,%1,%2,%3};\n"               \
        : "+f"((c)[0]), "+f"((c)[1]), "+f"((c)[2]), "+f"((c)[3])                \
        : "r"(a0), "r"(a1), "r"(a2), "r"(a3), "r"(b0), "r"(b1))

// ---------------------------------------------------------------------------
// Pre-pass kernels
// ---------------------------------------------------------------------------
__global__ void f32_to_f16(const float4* __restrict__ in, __half2* __restrict__ out, int n4) {
    int i = blockIdx.x * blockDim.x + threadIdx.x;
    if (i < n4) {
        float4 v = in[i];
        out[2 * i]     = __floats2half2_rn(v.x, v.y);
        out[2 * i + 1] = __floats2half2_rn(v.z, v.w);
    }
}

__global__ void transpose_h(const float* __restrict__ W, __half* __restrict__ Wt,
                            int Kdim, int Ndim) {
    __shared__ float t[32][33];
    const int n0 = blockIdx.x * 32, k0 = blockIdx.y * 32;
    const int x = threadIdx.x, y = threadIdx.y;
    #pragma unroll
    for (int i = 0; i < 32; i += 8)
        t[y + i][x] = W[(size_t)(k0 + y + i) * Ndim + n0 + x];
    __syncthreads();
    #pragma unroll
    for (int i = 0; i < 32; i += 8)
        Wt[(size_t)(n0 + y + i) * Kdim + k0 + x] = __float2half_rn(t[x][y + i]);
}

__global__ void build_bm(const float* __restrict__ mask, const float* __restrict__ bias,
                         float* __restrict__ bm) {
    int idx = blockIdx.x * 256 + threadIdx.x;
    const int TOT = 64 * 16 * 49 * 56;
    if (idx >= TOT) return;
    int m = idx % 56;
    int r = idx / 56;
    int l = r % 49;
    int wh = r / 49;
    int h = wh % 16;
    int win = wh / 16;
    float v = 0.f;
    if (m < 49) {
        int lh = l / 7, lw = l - lh * 7;
        int mh = m / 7, mw = m - mh * 7;
        int ri = (lh - mh + 6) * 13 + (lw - mw + 6);
        v = bias[ri * 16 + h] + mask[(win * 49 + l) * 49 + m];
    }
    bm[idx] = v;
}

// ---------------------------------------------------------------------------
// fp16 GEMM: C[M,N] = A[M,K] * Bt[N,K]^T, fp32 accumulate.
// BM=BN=128, BK=64 halves (128B rows), 3 stages x 32 KB dynamic smem,
// 256 threads (8 warps, 2m x 4n), warp tile 64x32, mma.m16n8k16.
// SW128 swizzle u ^ (row & 7); single barrier per k-tile.
// NEW (R13): register double-buffered fragments — ldsm for ks+1 issued
// before the mma block of ks, hiding LDS latency under tensor issue.
// ---------------------------------------------------------------------------
#define GSTG_B 32768
#define GB_HALF 16384
#define GSMEM (3 * GSTG_B)

template <bool OUT_HALF>
__global__ __launch_bounds__(256, 2)
void gemm_h(const __half* __restrict__ A, const __half* __restrict__ Bt,
            void* __restrict__ Cv, int M, int N, int K) {
    extern __shared__ __align__(16) char dsm[];

    const int tid = threadIdx.x, lane = tid & 31, warp = tid >> 5;
    const int wm = warp >> 2, wn = warp & 3;
    const int m0 = blockIdx.y * 128, n0 = blockIdx.x * 128;

    const int r_ld = tid >> 1;
    const int cb   = (tid & 1) * 4;
    const __half* ag = A  + (size_t)(m0 + r_ld) * K + cb * 8;
    const __half* bg = Bt + (size_t)(n0 + r_ld) * K + cb * 8;
    uint32_t adst[4], bdst[4];
    #pragma unroll
    for (int j = 0; j < 4; ++j) {
        adst[j] = (uint32_t)(r_ld * 128 + (((cb + j) ^ (r_ld & 7)) << 4));
        bdst[j] = GB_HALF + adst[j];
    }

    uint32_t sb[3];
    #pragma unroll
    for (int s = 0; s < 3; ++s) sb[s] = smem_u32(dsm) + s * GSTG_B;

    const int rr = lane & 7;
    const int mA = (lane >> 3) & 1;
    const int kU = lane >> 4;

    // Precomputed ldsm base addresses (k-unit varies by ks)
    uint32_t aAddr[4], bAddr[2];
    #pragma unroll
    for (int mt = 0; mt < 4; ++mt) {
        int r = wm * 64 + mt * 16 + mA * 8 + rr;
        aAddr[mt] = (uint32_t)(r * 128) + ((uint32_t)(r & 7) << 4);  // xor applied on u below
    }
    #pragma unroll
    for (int p = 0; p < 2; ++p) {
        int n = wn * 32 + p * 16 + kU * 8 + rr;
        bAddr[p] = (uint32_t)(n * 128) + ((uint32_t)(n & 7) << 4);
    }
    // NOTE: swizzle is u ^ (row&7); address = row*128 + ((u ^ (row&7))<<4).
    // We fold (row&7)<<4 into the base and XOR the shifted u at use site:
    // row*128 + ((u<<4) ^ ((row&7)<<4)) == row*128 + ((u ^ (row&7))<<4).

    float acc[16][4];
    #pragma unroll
    for (int i = 0; i < 16; ++i)
        #pragma unroll
        for (int j = 0; j < 4; ++j) acc[i][j] = 0.f;

    const int nK = K >> 6;

    #pragma unroll
    for (int p = 0; p < 2; ++p) {
        #pragma unroll
        for (int j = 0; j < 4; ++j) {
            cp_async16(sb[p] + adst[j], ag + p * 64 + j * 8);
            cp_async16(sb[p] + bdst[j], bg + p * 64 + j * 8);
        }
        CP_COMMIT();
    }

    uint32_t af[2][4][4], bf[2][2][4];

    for (int kt = 0; kt < nK; ++kt) {
        if (kt + 1 < nK) asm volatile("cp.async.wait_group 1;" ::: "memory");
        else             asm volatile("cp.async.wait_group 0;" ::: "memory");
        __syncthreads();

        if (kt + 2 < nK) {
            uint32_t so = sb[(kt + 2) % 3];
            #pragma unroll
            for (int j = 0; j < 4; ++j) {
                cp_async16(so + adst[j], ag + (kt + 2) * 64 + j * 8);
                cp_async16(so + bdst[j], bg + (kt + 2) * 64 + j * 8);
            }
            CP_COMMIT();
        }

        const uint32_t aB = sb[kt % 3];
        const uint32_t bB = aB + GB_HALF;

        // preload fragments for ks = 0
        {
            const uint32_t uA = (uint32_t)(0 * 2 + kU) << 4;
            const uint32_t uB = (uint32_t)(0 * 2 + mA) << 4;
            #pragma unroll
            for (int mt = 0; mt < 4; ++mt)
                ldsm_x4(aB + (aAddr[mt] ^ uA) + (aAddr[mt] & 0) , af[0][mt][0], af[0][mt][1], af[0][mt][2], af[0][mt][3]);
            #pragma unroll
            for (int p = 0; p < 2; ++p)
                ldsm_x4(bB + (bAddr[p] ^ uB), bf[0][p][0], bf[0][p][1], bf[0][p][2], bf[0][p][3]);
        }

        #pragma unroll
        for (int ks = 0; ks < 4; ++ks) {
            const int cur = ks & 1, nxt = cur ^ 1;
            if (ks < 3) {
                const uint32_t uA = (uint32_t)((ks + 1) * 2 + kU) << 4;
                const uint32_t uB = (uint32_t)((ks + 1) * 2 + mA) << 4;
                #pragma unroll
                for (int mt = 0; mt < 4; ++mt)
                    ldsm_x4(aB + (aAddr[mt] ^ uA), af[nxt][mt][0], af[nxt][mt][1],
                            af[nxt][mt][2], af[nxt][mt][3]);
                #pragma unroll
                for (int p = 0; p < 2; ++p)
                    ldsm_x4(bB + (bAddr[p] ^ uB), bf[nxt][p][0], bf[nxt][p][1],
                            bf[nxt][p][2], bf[nxt][p][3]);
            }
            #pragma unroll
            for (int mt = 0; mt < 4; ++mt)
                #pragma unroll
                for (int nt = 0; nt < 4; ++nt)
                    MMA_F16(acc[mt * 4 + nt],
                            af[cur][mt][0], af[cur][mt][1], af[cur][mt][2], af[cur][mt][3],
                            bf[cur][nt >> 1][(nt & 1) * 2], bf[cur][nt >> 1][(nt & 1) * 2 + 1]);
        }
    }

    const int g = lane >> 2, t = lane & 3;
    #pragma unroll
    for (int mt = 0; mt < 4; ++mt) {
        #pragma unroll
        for (int nt = 0; nt < 4; ++nt) {
            const float* c = acc[mt * 4 + nt];
            int r = m0 + wm * 64 + mt * 16 + g;
            int cc = n0 + wn * 32 + nt * 8 + t * 2;
            if (OUT_HALF) {
                __half* C = (__half*)Cv;
                *(__half2*)&C[(size_t)r * N + cc]       = __floats2half2_rn(c[0], c[1]);
                *(__half2*)&C[(size_t)(r + 8) * N + cc] = __floats2half2_rn(c[2], c[3]);
            } else {
                float* C = (float*)Cv;
                *(float2*)&C[(size_t)r * N + cc]       = make_float2(c[0], c[1]);
                *(float2*)&C[(size_t)(r + 8) * N + cc] = make_float2(c[2], c[3]);
            }
        }
    }
}

// ---------------------------------------------------------------------------
// fp16 tensor-core attention (R11/R12-proven). One CTA per (window, head).
// ---------------------------------------------------------------------------
#define QO 0
#define KO 4096
#define VO 8192
#define PO 12288
#define ATT_SMEM (12288 + 64 * 144)

__global__ __launch_bounds__(128, 6)
void attn_h(const __half* __restrict__ qkv, const float* __restrict__ bm,
            __half* __restrict__ att) {
    __shared__ __align__(16) char smc[ATT_SMEM];
    const uint32_t sb = smem_u32(smc);

    const int b = blockIdx.x, h = blockIdx.y;
    const int tid = threadIdx.x, lane = tid & 31, w = tid >> 5;

    const __half* base = qkv + (size_t)b * L_TOK * 1536 + h * HD_DIM;

    #pragma unroll
    for (int j = 0; j < 2; ++j) {
        int u = tid * 2 + j;
        int r = u >> 2, c = u & 3;
        uint32_t sz = (r < L_TOK) ? 16u : 0u;
        const __half* src = (r < L_TOK) ? (base + (size_t)r * 1536 + c * 8) : base;
        uint32_t dst = (uint32_t)(r * 64 + ((c ^ ((r >> 1) & 3)) << 4));
        cp_async16z(sb + QO + dst, src, sz);
        cp_async16z(sb + KO + dst, src + 512, sz);
        cp_async16z(sb + VO + dst, src + 1024, sz);
    }
    CP_COMMIT();
    asm volatile("cp.async.wait_group 0;" ::: "memory");
    __syncthreads();

    const int rr = lane & 7;
    const int mA = (lane >> 3) & 1;
    const int kU = lane >> 4;

    float sacc[8][4];
    #pragma unroll
    for (int j = 0; j < 8; ++j)
        #pragma unroll
        for (int r = 0; r < 4; ++r) sacc[j][r] = 0.f;

    #pragma unroll
    for (int ks = 0; ks < 2; ++ks) {
        uint32_t a[4];
        {
            int r = w * 16 + mA * 8 + rr;
            int u = ks * 2 + kU;
            ldsm_x4(sb + QO + (uint32_t)(r * 64 + ((u ^ ((r >> 1) & 3)) << 4)),
                    a[0], a[1], a[2], a[3]);
        }
        uint32_t bf[4][4];
        #pragma unroll
        for (int p = 0; p < 4; ++p) {
            int n = p * 16 + kU * 8 + rr;
            int u = ks * 2 + mA;
            ldsm_x4(sb + KO + (uint32_t)(n * 64 + ((u ^ ((n >> 1) & 3)) << 4)),
                    bf[p][0], bf[p][1], bf[p][2], bf[p][3]);
        }
        #pragma unroll
        for (int nt = 0; nt < 8; ++nt)
            MMA_F16(sacc[nt], a[0], a[1], a[2], a[3],
                    bf[nt >> 1][(nt & 1) * 2], bf[nt >> 1][(nt & 1) * 2 + 1]);
    }

    const int g = lane >> 2, t = lane & 3;
    const int l0 = w * 16 + g, l1 = l0 + 8;
    const int win = b & 63;
    const bool v0 = (l0 < L_TOK), v1 = (l1 < L_TOK);
    const int l0c = v0 ? l0 : 48, l1c = v1 ? l1 : 48;
    const float* bm0 = bm + (((size_t)win * 16 + h) * 49 + l0c) * 56;
    const float* bm1 = bm + (((size_t)win * 16 + h) * 49 + l1c) * 56;
    const float scale = 0.1767766952966369f;

    float mx0 = -1e30f, mx1 = -1e30f;
    #pragma unroll
    for (int j = 0; j < 8; ++j) {
        int ma = 8 * j + 2 * t;
        float* c = sacc[j];
        if (ma < L_TOK) {
            float2 ba = *(const float2*)&bm0[ma];
            float2 bb = *(const float2*)&bm1[ma];
            c[0] = v0 ? fmaf(c[0], scale, ba.x) : -1e30f;
            c[1] = (v0 && ma + 1 < L_TOK) ? fmaf(c[1], scale, ba.y) : -1e30f;
            c[2] = v1 ? fmaf(c[2], scale, bb.x) : -1e30f;
            c[3] = (v1 && ma + 1 < L_TOK) ? fmaf(c[3], scale, bb.y) : -1e30f;
        } else {
            c[0] = c[1] = c[2] = c[3] = -1e30f;
        }
        mx0 = fmaxf(mx0, fmaxf(c[0], c[1]));
        mx1 = fmaxf(mx1, fmaxf(c[2], c[3]));
    }
    mx0 = fmaxf(mx0, __shfl_xor_sync(0xffffffffu, mx0, 1));
    mx0 = fmaxf(mx0, __shfl_xor_sync(0xffffffffu, mx0, 2));
    mx1 = fmaxf(mx1, __shfl_xor_sync(0xffffffffu, mx1, 1));
    mx1 = fmaxf(mx1, __shfl_xor_sync(0xffffffffu, mx1, 2));

    float s0 = 0.f, s1 = 0.f;
    #pragma unroll
    for (int j = 0; j < 8; ++j) {
        float* c = sacc[j];
        c[0] = __expf(c[0] - mx0);
        c[1] = __expf(c[1] - mx0);
        c[2] = __expf(c[2] - mx1);
        c[3] = __expf(c[3] - mx1);
        s0 += c[0] + c[1];
        s1 += c[2] + c[3];
    }
    s0 += __shfl_xor_sync(0xffffffffu, s0, 1);
    s0 += __shfl_xor_sync(0xffffffffu, s0, 2);
    s1 += __shfl_xor_sync(0xffffffffu, s1, 1);
    s1 += __shfl_xor_sync(0xffffffffu, s1, 2);
    const float i0 = 1.f / s0, i1 = 1.f / s1;

    #pragma unroll
    for (int j = 0; j < 8; ++j) {
        float* c = sacc[j];
        int col = 8 * j + 2 * t;
        *(__half2*)(smc + PO + l0 * 144 + col * 2) = __floats2half2_rn(c[0] * i0, c[1] * i0);
        *(__half2*)(smc + PO + l1 * 144 + col * 2) = __floats2half2_rn(c[2] * i1, c[3] * i1);
    }
    __syncwarp();

    float oacc[4][4];
    #pragma unroll
    for (int nt = 0; nt < 4; ++nt)
        #pragma unroll
        for (int r = 0; r < 4; ++r) oacc[nt][r] = 0.f;

    #pragma unroll
    for (int ks = 0; ks < 4; ++ks) {
        uint32_t a[4];
        {
            int r = w * 16 + mA * 8 + rr;
            int u = ks * 2 + kU;
            ldsm_x4(sb + PO + (uint32_t)(r * 144 + u * 16), a[0], a[1], a[2], a[3]);
        }
        uint32_t bf[2][4];
        #pragma unroll
        for (int p = 0; p < 2; ++p) {
            int vr = ks * 16 + mA * 8 + rr;
            int u  = p * 2 + kU;
            ldsm_x4_t(sb + VO + (uint32_t)(vr * 64 + ((u ^ ((vr >> 1) & 3)) << 4)),
                      bf[p][0], bf[p][1], bf[p][2], bf[p][3]);
        }
        #pragma unroll
        for (int nt = 0; nt < 4; ++nt)
            MMA_F16(oacc[nt], a[0], a[1], a[2], a[3],
                    bf[nt >> 1][(nt & 1) * 2], bf[nt >> 1][(nt & 1) * 2 + 1]);
    }

    __half* orow0 = att + ((size_t)b * L_TOK + l0) * C_DIM + h * HD_DIM;
    __half* orow1 = orow0 + (size_t)8 * C_DIM;
    #pragma unroll
    for (int nt = 0; nt < 4; ++nt) {
        int d = nt * 8 + t * 2;
        if (v0) *(__half2*)(orow0 + d) = __floats2half2_rn(oacc[nt][0], oacc[nt][1]);
        if (v1) *(__half2*)(orow1 + d) = __floats2half2_rn(oacc[nt][2], oacc[nt][3]);
    }
}

// ---------------------------------------------------------------------------
// kernel_launch
// ---------------------------------------------------------------------------
extern "C" void kernel_launch(void* const* d_in, const int* in_sizes, int n_in,
                              void* d_out, int out_size) {
    const float* x     = (const float*)d_in[0];
    const float* mask  = (const float*)d_in[1];
    const float* bias  = (const float*)d_in[2];
    const float* wqkv  = (const float*)d_in[3];
    const float* wproj = (const float*)d_in[4];
    float*       out   = (float*)d_out;

    void *xh, *qkvh, *atth, *wqkvth, *wprojth, *bm;
    cudaGetSymbolAddress(&xh, g_xh);
    cudaGetSymbolAddress(&qkvh, g_qkvh);
    cudaGetSymbolAddress(&atth, g_atth);
    cudaGetSymbolAddress(&wqkvth, g_wqkvth);
    cudaGetSymbolAddress(&wprojth, g_wprojth);
    cudaGetSymbolAddress(&bm, g_bm);

    cudaFuncSetAttribute(gemm_h<true>,  cudaFuncAttributeMaxDynamicSharedMemorySize, GSMEM);
    cudaFuncSetAttribute(gemm_h<false>, cudaFuncAttributeMaxDynamicSharedMemorySize, GSMEM);

    // 0) Pre-passes
    const int n4 = ROWS * C_DIM / 4;
    f32_to_f16<<<(n4 + 255) / 256, 256>>>((const float4*)x, (__half2*)xh, n4);
    transpose_h<<<dim3(1536 / 32, 512 / 32), dim3(32, 8)>>>(wqkv, (__half*)wqkvth, C_DIM, 3 * C_DIM);
    transpose_h<<<dim3(512 / 32, 512 / 32), dim3(32, 8)>>>(wproj, (__half*)wprojth, C_DIM, C_DIM);
    const int bmTot = 64 * 16 * 49 * 56;
    build_bm<<<(bmTot + 255) / 256, 256>>>(mask, bias, (float*)bm);

    // 1) QKV projection
    gemm_h<true><<<dim3(1536 / 128, ROWS / 128), 256, GSMEM>>>(
        (const __half*)xh, (const __half*)wqkvth, qkvh, ROWS, 3 * C_DIM, C_DIM);

    // 2) Windowed attention
    attn_h<<<dim3(B_TOT, H_HEADS), 128>>>((const __half*)qkvh, (const float*)bm, (__half*)atth);

    // 3) Output projection (fp32 out)
    gemm_h<false><<<dim3(C_DIM / 128, ROWS / 128), 256, GSMEM>>>(
        (const __half*)atth, (const __half*)wprojth, out, ROWS, C_DIM, C_DIM);
}

// round 14
// speedup vs baseline: 1.0342x; 1.0342x over previous
#include <cuda_runtime.h>
#include <cuda_fp16.h>
#include <math.h>
#include <stdint.h>

// ---------------------------------------------------------------------------
// Problem constants
// ---------------------------------------------------------------------------
#define B_TOT   2048
#define L_TOK   49
#define C_DIM   512
#define H_HEADS 16
#define HD_DIM  32
#define ROWS    (B_TOT * L_TOK)        // 100352 = 784 * 128

// Scratch (device globals; allocation-free per harness rules)
static __device__ unsigned short g_xh[(size_t)ROWS * C_DIM];
static __device__ unsigned short g_qkvh[(size_t)ROWS * 3 * C_DIM];
static __device__ unsigned short g_atth[(size_t)ROWS * C_DIM];
static __device__ unsigned short g_wqkvth[3 * C_DIM * C_DIM];
static __device__ unsigned short g_wprojth[C_DIM * C_DIM];
static __device__ float g_bm[64 * 16 * 49 * 56];

// ---------------------------------------------------------------------------
// Helpers
// ---------------------------------------------------------------------------
__device__ __forceinline__ uint32_t smem_u32(const void* p) {
    uint32_t a;
    asm("{ .reg .u64 t; cvta.to.shared.u64 t, %1; cvt.u32.u64 %0, t; }" : "=r"(a) : "l"(p));
    return a;
}

__device__ __forceinline__ void ldsm_x4(uint32_t addr, uint32_t& r0, uint32_t& r1,
                                        uint32_t& r2, uint32_t& r3) {
    asm volatile("ldmatrix.sync.aligned.m8n8.x4.shared.b16 {%0,%1,%2,%3}, [%4];"
                 : "=r"(r0), "=r"(r1), "=r"(r2), "=r"(r3) : "r"(addr));
}

__device__ __forceinline__ void ldsm_x4_t(uint32_t addr, uint32_t& r0, uint32_t& r1,
                                          uint32_t& r2, uint32_t& r3) {
    asm volatile("ldmatrix.sync.aligned.m8n8.x4.trans.shared.b16 {%0,%1,%2,%3}, [%4];"
                 : "=r"(r0), "=r"(r1), "=r"(r2), "=r"(r3) : "r"(addr));
}

__device__ __forceinline__ void cp_async16(uint32_t d, const void* s) {
    asm volatile("cp.async.cg.shared.global [%0], [%1], 16;" :: "r"(d), "l"(s) : "memory");
}
__device__ __forceinline__ void cp_async16z(uint32_t d, const void* s, uint32_t sz) {
    asm volatile("cp.async.cg.shared.global [%0], [%1], 16, %2;"
                 :: "r"(d), "l"(s), "r"(sz) : "memory");
}
#define CP_COMMIT() asm volatile("cp.async.commit_group;" ::: "memory")

#define MMA_F16(c, a0, a1, a2, a3, b0, b1)                                      \
    asm volatile(                                                               \
        "mma.sync.aligned.m16n8k16.row.col.f32.f16.f16.f32 "                    \
        "{%0,%1,%2,%3}, {%4,%5,%6,%7}, {%8,%9}, {%0,%1,%2,%3};\n"               \
        : "+f"((c)[0]), "+f"((c)[1]), "+f"((c)[2]), "+f"((c)[3])                \
        : "r"(a0), "r"(a1), "r"(a2), "r"(a3), "r"(b0), "r"(b1))

// ---------------------------------------------------------------------------
// Pre-pass kernels
// ---------------------------------------------------------------------------
__global__ void f32_to_f16(const float4* __restrict__ in, __half2* __restrict__ out, int n4) {
    int i = blockIdx.x * blockDim.x + threadIdx.x;
    if (i < n4) {
        float4 v = in[i];
        out[2 * i]     = __floats2half2_rn(v.x, v.y);
        out[2 * i + 1] = __floats2half2_rn(v.z, v.w);
    }
}

__global__ void transpose_h(const float* __restrict__ W, __half* __restrict__ Wt,
                            int Kdim, int Ndim) {
    __shared__ float t[32][33];
    const int n0 = blockIdx.x * 32, k0 = blockIdx.y * 32;
    const int x = threadIdx.x, y = threadIdx.y;
    #pragma unroll
    for (int i = 0; i < 32; i += 8)
        t[y + i][x] = W[(size_t)(k0 + y + i) * Ndim + n0 + x];
    __syncthreads();
    #pragma unroll
    for (int i = 0; i < 32; i += 8)
        Wt[(size_t)(n0 + y + i) * Kdim + k0 + x] = __float2half_rn(t[x][y + i]);
}

__global__ void build_bm(const float* __restrict__ mask, const float* __restrict__ bias,
                         float* __restrict__ bm) {
    int idx = blockIdx.x * 256 + threadIdx.x;
    const int TOT = 64 * 16 * 49 * 56;
    if (idx >= TOT) return;
    int m = idx % 56;
    int r = idx / 56;
    int l = r % 49;
    int wh = r / 49;
    int h = wh % 16;
    int win = wh / 16;
    float v = 0.f;
    if (m < 49) {
        int lh = l / 7, lw = l - lh * 7;
        int mh = m / 7, mw = m - mh * 7;
        int ri = (lh - mh + 6) * 13 + (lw - mw + 6);
        v = bias[ri * 16 + h] + mask[(win * 49 + l) * 49 + m];
    }
    bm[idx] = v;
}

// ---------------------------------------------------------------------------
// fp16 GEMM (R12-proven): C[M,N] = A[M,K] * Bt[N,K]^T, fp32 accumulate.
// BM=BN=128, BK=64 halves (128B rows), 3 stages x 32 KB dynamic smem,
// 256 threads (8 warps, 2m x 4n), warp tile 64x32, mma.m16n8k16.
// SW128 swizzle u ^ (row & 7); single barrier per k-tile.
// ---------------------------------------------------------------------------
#define GSTG_B 32768
#define GB_HALF 16384
#define GSMEM (3 * GSTG_B)

template <bool OUT_HALF>
__global__ __launch_bounds__(256, 2)
void gemm_h(const __half* __restrict__ A, const __half* __restrict__ Bt,
            void* __restrict__ Cv, int M, int N, int K) {
    extern __shared__ __align__(16) char dsm[];

    const int tid = threadIdx.x, lane = tid & 31, warp = tid >> 5;
    const int wm = warp >> 2, wn = warp & 3;
    const int m0 = blockIdx.y * 128, n0 = blockIdx.x * 128;

    const int r_ld = tid >> 1;
    const int cb   = (tid & 1) * 4;
    const __half* ag = A  + (size_t)(m0 + r_ld) * K + cb * 8;
    const __half* bg = Bt + (size_t)(n0 + r_ld) * K + cb * 8;
    uint32_t adst[4], bdst[4];
    #pragma unroll
    for (int j = 0; j < 4; ++j) {
        adst[j] = (uint32_t)(r_ld * 128 + (((cb + j) ^ (r_ld & 7)) << 4));
        bdst[j] = GB_HALF + adst[j];
    }

    uint32_t sb[3];
    #pragma unroll
    for (int s = 0; s < 3; ++s) sb[s] = smem_u32(dsm) + s * GSTG_B;

    const int rr = lane & 7;
    const int mA = (lane >> 3) & 1;
    const int kU = lane >> 4;

    float acc[16][4];
    #pragma unroll
    for (int i = 0; i < 16; ++i)
        #pragma unroll
        for (int j = 0; j < 4; ++j) acc[i][j] = 0.f;

    const int nK = K >> 6;

    #pragma unroll
    for (int p = 0; p < 2; ++p) {
        #pragma unroll
        for (int j = 0; j < 4; ++j) {
            cp_async16(sb[p] + adst[j], ag + p * 64 + j * 8);
            cp_async16(sb[p] + bdst[j], bg + p * 64 + j * 8);
        }
        CP_COMMIT();
    }

    for (int kt = 0; kt < nK; ++kt) {
        if (kt + 1 < nK) asm volatile("cp.async.wait_group 1;" ::: "memory");
        else             asm volatile("cp.async.wait_group 0;" ::: "memory");
        __syncthreads();

        if (kt + 2 < nK) {
            uint32_t so = sb[(kt + 2) % 3];
            #pragma unroll
            for (int j = 0; j < 4; ++j) {
                cp_async16(so + adst[j], ag + (kt + 2) * 64 + j * 8);
                cp_async16(so + bdst[j], bg + (kt + 2) * 64 + j * 8);
            }
            CP_COMMIT();
        }

        const uint32_t aB = sb[kt % 3];
        const uint32_t bB = aB + GB_HALF;

        #pragma unroll
        for (int ks = 0; ks < 4; ++ks) {
            uint32_t af[4][4];
            #pragma unroll
            for (int mt = 0; mt < 4; ++mt) {
                int r = wm * 64 + mt * 16 + mA * 8 + rr;
                int u = ks * 2 + kU;
                ldsm_x4(aB + (uint32_t)(r * 128 + ((u ^ (r & 7)) << 4)),
                        af[mt][0], af[mt][1], af[mt][2], af[mt][3]);
            }
            uint32_t bf[2][4];
            #pragma unroll
            for (int p = 0; p < 2; ++p) {
                int n = wn * 32 + p * 16 + kU * 8 + rr;
                int u = ks * 2 + mA;
                ldsm_x4(bB + (uint32_t)(n * 128 + ((u ^ (n & 7)) << 4)),
                        bf[p][0], bf[p][1], bf[p][2], bf[p][3]);
            }
            #pragma unroll
            for (int mt = 0; mt < 4; ++mt)
                #pragma unroll
                for (int nt = 0; nt < 4; ++nt)
                    MMA_F16(acc[mt * 4 + nt],
                            af[mt][0], af[mt][1], af[mt][2], af[mt][3],
                            bf[nt >> 1][(nt & 1) * 2], bf[nt >> 1][(nt & 1) * 2 + 1]);
        }
    }

    const int g = lane >> 2, t = lane & 3;
    #pragma unroll
    for (int mt = 0; mt < 4; ++mt) {
        #pragma unroll
        for (int nt = 0; nt < 4; ++nt) {
            const float* c = acc[mt * 4 + nt];
            int r = m0 + wm * 64 + mt * 16 + g;
            int cc = n0 + wn * 32 + nt * 8 + t * 2;
            if (OUT_HALF) {
                __half* C = (__half*)Cv;
                *(__half2*)&C[(size_t)r * N + cc]       = __floats2half2_rn(c[0], c[1]);
                *(__half2*)&C[(size_t)(r + 8) * N + cc] = __floats2half2_rn(c[2], c[3]);
            } else {
                float* C = (float*)Cv;
                *(float2*)&C[(size_t)r * N + cc]       = make_float2(c[0], c[1]);
                *(float2*)&C[(size_t)(r + 8) * N + cc] = make_float2(c[2], c[3]);
            }
        }
    }
}

// ---------------------------------------------------------------------------
// fp16 tensor-core attention. One CTA per (window b, head h); 128 thr, 4 warps.
// NEW (R14): P is fed to the PV mma DIRECTLY from the QK accumulator
// registers (QK accumulator layout == PV A-fragment layout for m16n8k16):
//   sacc[2ks]   -> a0 (row g,  cols 16ks+2t), a1 (row g+8)
//   sacc[2ks+1] -> a2 (row g,  cols 16ks+8+2t), a3 (row g+8)
// No P smem region, no __syncwarp, no PV A-ldsm.
// Smem: Q [64][64B] @0, K @4096, V [64][64B] @8192 (row-major). 12.3 KB.
// ---------------------------------------------------------------------------
#define QO 0
#define KO 4096
#define VO 8192
#define ATT_SMEM 12288

__global__ __launch_bounds__(128, 6)
void attn_h(const __half* __restrict__ qkv, const float* __restrict__ bm,
            __half* __restrict__ att) {
    __shared__ __align__(16) char smc[ATT_SMEM];
    const uint32_t sb = smem_u32(smc);

    const int b = blockIdx.x, h = blockIdx.y;
    const int tid = threadIdx.x, lane = tid & 31, w = tid >> 5;

    const __half* base = qkv + (size_t)b * L_TOK * 1536 + h * HD_DIM;

    #pragma unroll
    for (int j = 0; j < 2; ++j) {
        int u = tid * 2 + j;
        int r = u >> 2, c = u & 3;
        uint32_t sz = (r < L_TOK) ? 16u : 0u;
        const __half* src = (r < L_TOK) ? (base + (size_t)r * 1536 + c * 8) : base;
        uint32_t dst = (uint32_t)(r * 64 + ((c ^ ((r >> 1) & 3)) << 4));
        cp_async16z(sb + QO + dst, src, sz);
        cp_async16z(sb + KO + dst, src + 512, sz);
        cp_async16z(sb + VO + dst, src + 1024, sz);
    }
    CP_COMMIT();
    asm volatile("cp.async.wait_group 0;" ::: "memory");
    __syncthreads();

    const int rr = lane & 7;
    const int mA = (lane >> 3) & 1;
    const int kU = lane >> 4;

    // ---- QK^T: warp w -> rows w*16..+16, cols 0..63 ----
    float sacc[8][4];
    #pragma unroll
    for (int j = 0; j < 8; ++j)
        #pragma unroll
        for (int r = 0; r < 4; ++r) sacc[j][r] = 0.f;

    #pragma unroll
    for (int ks = 0; ks < 2; ++ks) {
        uint32_t a[4];
        {
            int r = w * 16 + mA * 8 + rr;
            int u = ks * 2 + kU;
            ldsm_x4(sb + QO + (uint32_t)(r * 64 + ((u ^ ((r >> 1) & 3)) << 4)),
                    a[0], a[1], a[2], a[3]);
        }
        uint32_t bf[4][4];
        #pragma unroll
        for (int p = 0; p < 4; ++p) {
            int n = p * 16 + kU * 8 + rr;
            int u = ks * 2 + mA;
            ldsm_x4(sb + KO + (uint32_t)(n * 64 + ((u ^ ((n >> 1) & 3)) << 4)),
                    bf[p][0], bf[p][1], bf[p][2], bf[p][3]);
        }
        #pragma unroll
        for (int nt = 0; nt < 8; ++nt)
            MMA_F16(sacc[nt], a[0], a[1], a[2], a[3],
                    bf[nt >> 1][(nt & 1) * 2], bf[nt >> 1][(nt & 1) * 2 + 1]);
    }

    // ---- scale + (bias+mask) + softmax (register resident) ----
    const int g = lane >> 2, t = lane & 3;
    const int l0 = w * 16 + g, l1 = l0 + 8;
    const int win = b & 63;
    const bool v0 = (l0 < L_TOK), v1 = (l1 < L_TOK);
    const int l0c = v0 ? l0 : 48, l1c = v1 ? l1 : 48;
    const float* bm0 = bm + (((size_t)win * 16 + h) * 49 + l0c) * 56;
    const float* bm1 = bm + (((size_t)win * 16 + h) * 49 + l1c) * 56;
    const float scale = 0.1767766952966369f;

    float mx0 = -1e30f, mx1 = -1e30f;
    #pragma unroll
    for (int j = 0; j < 8; ++j) {
        int ma = 8 * j + 2 * t;
        float* c = sacc[j];
        if (ma < L_TOK) {
            float2 ba = *(const float2*)&bm0[ma];
            float2 bb = *(const float2*)&bm1[ma];
            c[0] = v0 ? fmaf(c[0], scale, ba.x) : -1e30f;
            c[1] = (v0 && ma + 1 < L_TOK) ? fmaf(c[1], scale, ba.y) : -1e30f;
            c[2] = v1 ? fmaf(c[2], scale, bb.x) : -1e30f;
            c[3] = (v1 && ma + 1 < L_TOK) ? fmaf(c[3], scale, bb.y) : -1e30f;
        } else {
            c[0] = c[1] = c[2] = c[3] = -1e30f;
        }
        mx0 = fmaxf(mx0, fmaxf(c[0], c[1]));
        mx1 = fmaxf(mx1, fmaxf(c[2], c[3]));
    }
    mx0 = fmaxf(mx0, __shfl_xor_sync(0xffffffffu, mx0, 1));
    mx0 = fmaxf(mx0, __shfl_xor_sync(0xffffffffu, mx0, 2));
    mx1 = fmaxf(mx1, __shfl_xor_sync(0xffffffffu, mx1, 1));
    mx1 = fmaxf(mx1, __shfl_xor_sync(0xffffffffu, mx1, 2));

    float s0 = 0.f, s1 = 0.f;
    #pragma unroll
    for (int j = 0; j < 8; ++j) {
        float* c = sacc[j];
        c[0] = __expf(c[0] - mx0);
        c[1] = __expf(c[1] - mx0);
        c[2] = __expf(c[2] - mx1);
        c[3] = __expf(c[3] - mx1);
        s0 += c[0] + c[1];
        s1 += c[2] + c[3];
    }
    s0 += __shfl_xor_sync(0xffffffffu, s0, 1);
    s0 += __shfl_xor_sync(0xffffffffu, s0, 2);
    s1 += __shfl_xor_sync(0xffffffffu, s1, 1);
    s1 += __shfl_xor_sync(0xffffffffu, s1, 2);
    const float i0 = 1.f / s0, i1 = 1.f / s1;

    // ---- O = P @ V : P fed directly from registers ----
    float oacc[4][4];
    #pragma unroll
    for (int nt = 0; nt < 4; ++nt)
        #pragma unroll
        for (int r = 0; r < 4; ++r) oacc[nt][r] = 0.f;

    #pragma unroll
    for (int ks = 0; ks < 4; ++ks) {
        // Pack P fragments from QK accumulators (identical rounding to the
        // old store-to-smem path: __floats2half2_rn of c*inv).
        __half2 pa0 = __floats2half2_rn(sacc[2 * ks][0] * i0,     sacc[2 * ks][1] * i0);
        __half2 pa1 = __floats2half2_rn(sacc[2 * ks][2] * i1,     sacc[2 * ks][3] * i1);
        __half2 pa2 = __floats2half2_rn(sacc[2 * ks + 1][0] * i0, sacc[2 * ks + 1][1] * i0);
        __half2 pa3 = __floats2half2_rn(sacc[2 * ks + 1][2] * i1, sacc[2 * ks + 1][3] * i1);
        uint32_t a0 = *(uint32_t*)&pa0, a1 = *(uint32_t*)&pa1;
        uint32_t a2 = *(uint32_t*)&pa2, a3 = *(uint32_t*)&pa3;

        uint32_t bf[2][4];
        #pragma unroll
        for (int p = 0; p < 2; ++p) {
            int vr = ks * 16 + mA * 8 + rr;      // V source row (= k index)
            int u  = p * 2 + kU;                 // d-unit
            ldsm_x4_t(sb + VO + (uint32_t)(vr * 64 + ((u ^ ((vr >> 1) & 3)) << 4)),
                      bf[p][0], bf[p][1], bf[p][2], bf[p][3]);
        }
        #pragma unroll
        for (int nt = 0; nt < 4; ++nt)
            MMA_F16(oacc[nt], a0, a1, a2, a3,
                    bf[nt >> 1][(nt & 1) * 2], bf[nt >> 1][(nt & 1) * 2 + 1]);
    }

    // ---- write merged-head output (fp16, feeds proj GEMM) ----
    __half* orow0 = att + ((size_t)b * L_TOK + l0) * C_DIM + h * HD_DIM;
    __half* orow1 = orow0 + (size_t)8 * C_DIM;
    #pragma unroll
    for (int nt = 0; nt < 4; ++nt) {
        int d = nt * 8 + t * 2;
        if (v0) *(__half2*)(orow0 + d) = __floats2half2_rn(oacc[nt][0], oacc[nt][1]);
        if (v1) *(__half2*)(orow1 + d) = __floats2half2_rn(oacc[nt][2], oacc[nt][3]);
    }
}

// ---------------------------------------------------------------------------
// kernel_launch
// ---------------------------------------------------------------------------
extern "C" void kernel_launch(void* const* d_in, const int* in_sizes, int n_in,
                              void* d_out, int out_size) {
    const float* x     = (const float*)d_in[0];
    const float* mask  = (const float*)d_in[1];
    const float* bias  = (const float*)d_in[2];
    const float* wqkv  = (const float*)d_in[3];
    const float* wproj = (const float*)d_in[4];
    float*       out   = (float*)d_out;

    void *xh, *qkvh, *atth, *wqkvth, *wprojth, *bm;
    cudaGetSymbolAddress(&xh, g_xh);
    cudaGetSymbolAddress(&qkvh, g_qkvh);
    cudaGetSymbolAddress(&atth, g_atth);
    cudaGetSymbolAddress(&wqkvth, g_wqkvth);
    cudaGetSymbolAddress(&wprojth, g_wprojth);
    cudaGetSymbolAddress(&bm, g_bm);

    cudaFuncSetAttribute(gemm_h<true>,  cudaFuncAttributeMaxDynamicSharedMemorySize, GSMEM);
    cudaFuncSetAttribute(gemm_h<false>, cudaFuncAttributeMaxDynamicSharedMemorySize, GSMEM);

    // 0) Pre-passes
    const int n4 = ROWS * C_DIM / 4;
    f32_to_f16<<<(n4 + 255) / 256, 256>>>((const float4*)x, (__half2*)xh, n4);
    transpose_h<<<dim3(1536 / 32, 512 / 32), dim3(32, 8)>>>(wqkv, (__half*)wqkvth, C_DIM, 3 * C_DIM);
    transpose_h<<<dim3(512 / 32, 512 / 32), dim3(32, 8)>>>(wproj, (__half*)wprojth, C_DIM, C_DIM);
    const int bmTot = 64 * 16 * 49 * 56;
    build_bm<<<(bmTot + 255) / 256, 256>>>(mask, bias, (float*)bm);

    // 1) QKV projection
    gemm_h<true><<<dim3(1536 / 128, ROWS / 128), 256, GSMEM>>>(
        (const __half*)xh, (const __half*)wqkvth, qkvh, ROWS, 3 * C_DIM, C_DIM);

    // 2) Windowed attention (P register-direct)
    attn_h<<<dim3(B_TOT, H_HEADS), 128>>>((const __half*)qkvh, (const float*)bm, (__half*)atth);

    // 3) Output projection (fp32 out)
    gemm_h<false><<<dim3(C_DIM / 128, ROWS / 128), 256, GSMEM>>>(
        (const __half*)atth, (const __half*)wprojth, out, ROWS, C_DIM, C_DIM);
}

// round 15
// speedup vs baseline: 1.0450x; 1.0104x over previous
#include <cuda_runtime.h>
#include <cuda_fp16.h>
#include <math.h>
#include <stdint.h>

// ---------------------------------------------------------------------------
// Problem constants
// ---------------------------------------------------------------------------
#define B_TOT   2048
#define L_TOK   49
#define C_DIM   512
#define H_HEADS 16
#define HD_DIM  32
#define ROWS    (B_TOT * L_TOK)        // 100352 = 784 * 128

// Scratch (device globals; allocation-free per harness rules)
static __device__ unsigned short g_xh[(size_t)ROWS * C_DIM];
static __device__ unsigned short g_qkvh[(size_t)ROWS * 3 * C_DIM];
static __device__ unsigned short g_atth[(size_t)ROWS * C_DIM];
static __device__ unsigned short g_wqkvth[3 * C_DIM * C_DIM];
static __device__ unsigned short g_wprojth[C_DIM * C_DIM];
static __device__ unsigned short g_bm[64 * 16 * 49 * 56];      // fp16 bias+mask

// ---------------------------------------------------------------------------
// Helpers
// ---------------------------------------------------------------------------
__device__ __forceinline__ uint32_t smem_u32(const void* p) {
    uint32_t a;
    asm("{ .reg .u64 t; cvta.to.shared.u64 t, %1; cvt.u32.u64 %0, t; }" : "=r"(a) : "l"(p));
    return a;
}

__device__ __forceinline__ void ldsm_x4(uint32_t addr, uint32_t& r0, uint32_t& r1,
                                        uint32_t& r2, uint32_t& r3) {
    asm volatile("ldmatrix.sync.aligned.m8n8.x4.shared.b16 {%0,%1,%2,%3}, [%4];"
                 : "=r"(r0), "=r"(r1), "=r"(r2), "=r"(r3) : "r"(addr));
}

__device__ __forceinline__ void ldsm_x4_t(uint32_t addr, uint32_t& r0, uint32_t& r1,
                                          uint32_t& r2, uint32_t& r3) {
    asm volatile("ldmatrix.sync.aligned.m8n8.x4.trans.shared.b16 {%0,%1,%2,%3}, [%4];"
                 : "=r"(r0), "=r"(r1), "=r"(r2), "=r"(r3) : "r"(addr));
}

__device__ __forceinline__ void cp_async16(uint32_t d, const void* s) {
    asm volatile("cp.async.cg.shared.global [%0], [%1], 16;" :: "r"(d), "l"(s) : "memory");
}
__device__ __forceinline__ void cp_async16z(uint32_t d, const void* s, uint32_t sz) {
    asm volatile("cp.async.cg.shared.global [%0], [%1], 16, %2;"
                 :: "r"(d), "l"(s), "r"(sz) : "memory");
}
#define CP_COMMIT() asm volatile("cp.async.commit_group;" ::: "memory")

#define MMA_F16(c, a0, a1, a2, a3, b0, b1)                                      \
    asm volatile(                                                               \
        "mma.sync.aligned.m16n8k16.row.col.f32.f16.f16.f32 "                    \
        "{%0,%1,%2,%3}, {%4,%5,%6,%7}, {%8,%9}, {%0,%1,%2,%3};\n"               \
        : "+f"((c)[0]), "+f"((c)[1]), "+f"((c)[2]), "+f"((c)[3])                \
        : "r"(a0), "r"(a1), "r"(a2), "r"(a3), "r"(b0), "r"(b1))

// ---------------------------------------------------------------------------
// Pre-pass kernels
// ---------------------------------------------------------------------------
__global__ void f32_to_f16(const float4* __restrict__ in, __half2* __restrict__ out, int n4) {
    int i = blockIdx.x * blockDim.x + threadIdx.x;
    if (i < n4) {
        float4 v = in[i];
        out[2 * i]     = __floats2half2_rn(v.x, v.y);
        out[2 * i + 1] = __floats2half2_rn(v.z, v.w);
    }
}

__global__ void transpose_h(const float* __restrict__ W, __half* __restrict__ Wt,
                            int Kdim, int Ndim) {
    __shared__ float t[32][33];
    const int n0 = blockIdx.x * 32, k0 = blockIdx.y * 32;
    const int x = threadIdx.x, y = threadIdx.y;
    #pragma unroll
    for (int i = 0; i < 32; i += 8)
        t[y + i][x] = W[(size_t)(k0 + y + i) * Ndim + n0 + x];
    __syncthreads();
    #pragma unroll
    for (int i = 0; i < 32; i += 8)
        Wt[(size_t)(n0 + y + i) * Kdim + k0 + x] = __float2half_rn(t[x][y + i]);
}

__global__ void build_bm(const float* __restrict__ mask, const float* __restrict__ bias,
                         __half* __restrict__ bm) {
    int idx = blockIdx.x * 256 + threadIdx.x;
    const int TOT = 64 * 16 * 49 * 56;
    if (idx >= TOT) return;
    int m = idx % 56;
    int r = idx / 56;
    int l = r % 49;
    int wh = r / 49;
    int h = wh % 16;
    int win = wh / 16;
    float v = 0.f;
    if (m < 49) {
        int lh = l / 7, lw = l - lh * 7;
        int mh = m / 7, mw = m - mh * 7;
        int ri = (lh - mh + 6) * 13 + (lw - mw + 6);
        v = bias[ri * 16 + h] + mask[(win * 49 + l) * 49 + m];
    }
    bm[idx] = __float2half_rn(v);
}

// ---------------------------------------------------------------------------
// fp16 GEMM (R12-proven): C[M,N] = A[M,K] * Bt[N,K]^T, fp32 accumulate.
// BM=BN=128, BK=64 halves (128B rows), 3 stages x 32 KB dynamic smem,
// 256 threads (8 warps, 2m x 4n), warp tile 64x32, mma.m16n8k16.
// SW128 swizzle u ^ (row & 7); single barrier per k-tile.
// ---------------------------------------------------------------------------
#define GSTG_B 32768
#define GB_HALF 16384
#define GSMEM (3 * GSTG_B)

template <bool OUT_HALF>
__global__ __launch_bounds__(256, 2)
void gemm_h(const __half* __restrict__ A, const __half* __restrict__ Bt,
            void* __restrict__ Cv, int M, int N, int K) {
    extern __shared__ __align__(16) char dsm[];

    const int tid = threadIdx.x, lane = tid & 31, warp = tid >> 5;
    const int wm = warp >> 2, wn = warp & 3;
    const int m0 = blockIdx.y * 128, n0 = blockIdx.x * 128;

    const int r_ld = tid >> 1;
    const int cb   = (tid & 1) * 4;
    const __half* ag = A  + (size_t)(m0 + r_ld) * K + cb * 8;
    const __half* bg = Bt + (size_t)(n0 + r_ld) * K + cb * 8;
    uint32_t adst[4], bdst[4];
    #pragma unroll
    for (int j = 0; j < 4; ++j) {
        adst[j] = (uint32_t)(r_ld * 128 + (((cb + j) ^ (r_ld & 7)) << 4));
        bdst[j] = GB_HALF + adst[j];
    }

    uint32_t sb[3];
    #pragma unroll
    for (int s = 0; s < 3; ++s) sb[s] = smem_u32(dsm) + s * GSTG_B;

    const int rr = lane & 7;
    const int mA = (lane >> 3) & 1;
    const int kU = lane >> 4;

    float acc[16][4];
    #pragma unroll
    for (int i = 0; i < 16; ++i)
        #pragma unroll
        for (int j = 0; j < 4; ++j) acc[i][j] = 0.f;

    const int nK = K >> 6;

    #pragma unroll
    for (int p = 0; p < 2; ++p) {
        #pragma unroll
        for (int j = 0; j < 4; ++j) {
            cp_async16(sb[p] + adst[j], ag + p * 64 + j * 8);
            cp_async16(sb[p] + bdst[j], bg + p * 64 + j * 8);
        }
        CP_COMMIT();
    }

    for (int kt = 0; kt < nK; ++kt) {
        if (kt + 1 < nK) asm volatile("cp.async.wait_group 1;" ::: "memory");
        else             asm volatile("cp.async.wait_group 0;" ::: "memory");
        __syncthreads();

        if (kt + 2 < nK) {
            uint32_t so = sb[(kt + 2) % 3];
            #pragma unroll
            for (int j = 0; j < 4; ++j) {
                cp_async16(so + adst[j], ag + (kt + 2) * 64 + j * 8);
                cp_async16(so + bdst[j], bg + (kt + 2) * 64 + j * 8);
            }
            CP_COMMIT();
        }

        const uint32_t aB = sb[kt % 3];
        const uint32_t bB = aB + GB_HALF;

        #pragma unroll
        for (int ks = 0; ks < 4; ++ks) {
            uint32_t af[4][4];
            #pragma unroll
            for (int mt = 0; mt < 4; ++mt) {
                int r = wm * 64 + mt * 16 + mA * 8 + rr;
                int u = ks * 2 + kU;
                ldsm_x4(aB + (uint32_t)(r * 128 + ((u ^ (r & 7)) << 4)),
                        af[mt][0], af[mt][1], af[mt][2], af[mt][3]);
            }
            uint32_t bf[2][4];
            #pragma unroll
            for (int p = 0; p < 2; ++p) {
                int n = wn * 32 + p * 16 + kU * 8 + rr;
                int u = ks * 2 + mA;
                ldsm_x4(bB + (uint32_t)(n * 128 + ((u ^ (n & 7)) << 4)),
                        bf[p][0], bf[p][1], bf[p][2], bf[p][3]);
            }
            #pragma unroll
            for (int mt = 0; mt < 4; ++mt)
                #pragma unroll
                for (int nt = 0; nt < 4; ++nt)
                    MMA_F16(acc[mt * 4 + nt],
                            af[mt][0], af[mt][1], af[mt][2], af[mt][3],
                            bf[nt >> 1][(nt & 1) * 2], bf[nt >> 1][(nt & 1) * 2 + 1]);
        }
    }

    const int g = lane >> 2, t = lane & 3;
    #pragma unroll
    for (int mt = 0; mt < 4; ++mt) {
        #pragma unroll
        for (int nt = 0; nt < 4; ++nt) {
            const float* c = acc[mt * 4 + nt];
            int r = m0 + wm * 64 + mt * 16 + g;
            int cc = n0 + wn * 32 + nt * 8 + t * 2;
            if (OUT_HALF) {
                __half* C = (__half*)Cv;
                *(__half2*)&C[(size_t)r * N + cc]       = __floats2half2_rn(c[0], c[1]);
                *(__half2*)&C[(size_t)(r + 8) * N + cc] = __floats2half2_rn(c[2], c[3]);
            } else {
                float* C = (float*)Cv;
                *(float2*)&C[(size_t)r * N + cc]       = make_float2(c[0], c[1]);
                *(float2*)&C[(size_t)(r + 8) * N + cc] = make_float2(c[2], c[3]);
            }
        }
    }
}

// ---------------------------------------------------------------------------
// fp16 tensor-core attention (R14-proven register-direct P), bm table fp16.
// One CTA per (window b, head h); 128 threads, 4 warps.
// Smem: Q [64][64B] @0, K @4096, V [64][64B] @8192 (row-major). 12.3 KB.
// ---------------------------------------------------------------------------
#define QO 0
#define KO 4096
#define VO 8192
#define ATT_SMEM 12288

__global__ __launch_bounds__(128, 6)
void attn_h(const __half* __restrict__ qkv, const __half* __restrict__ bm,
            __half* __restrict__ att) {
    __shared__ __align__(16) char smc[ATT_SMEM];
    const uint32_t sb = smem_u32(smc);

    const int b = blockIdx.x, h = blockIdx.y;
    const int tid = threadIdx.x, lane = tid & 31, w = tid >> 5;

    const __half* base = qkv + (size_t)b * L_TOK * 1536 + h * HD_DIM;

    #pragma unroll
    for (int j = 0; j < 2; ++j) {
        int u = tid * 2 + j;
        int r = u >> 2, c = u & 3;
        uint32_t sz = (r < L_TOK) ? 16u : 0u;
        const __half* src = (r < L_TOK) ? (base + (size_t)r * 1536 + c * 8) : base;
        uint32_t dst = (uint32_t)(r * 64 + ((c ^ ((r >> 1) & 3)) << 4));
        cp_async16z(sb + QO + dst, src, sz);
        cp_async16z(sb + KO + dst, src + 512, sz);
        cp_async16z(sb + VO + dst, src + 1024, sz);
    }
    CP_COMMIT();
    asm volatile("cp.async.wait_group 0;" ::: "memory");
    __syncthreads();

    const int rr = lane & 7;
    const int mA = (lane >> 3) & 1;
    const int kU = lane >> 4;

    // ---- QK^T: warp w -> rows w*16..+16, cols 0..63 ----
    float sacc[8][4];
    #pragma unroll
    for (int j = 0; j < 8; ++j)
        #pragma unroll
        for (int r = 0; r < 4; ++r) sacc[j][r] = 0.f;

    #pragma unroll
    for (int ks = 0; ks < 2; ++ks) {
        uint32_t a[4];
        {
            int r = w * 16 + mA * 8 + rr;
            int u = ks * 2 + kU;
            ldsm_x4(sb + QO + (uint32_t)(r * 64 + ((u ^ ((r >> 1) & 3)) << 4)),
                    a[0], a[1], a[2], a[3]);
        }
        uint32_t bf[4][4];
        #pragma unroll
        for (int p = 0; p < 4; ++p) {
            int n = p * 16 + kU * 8 + rr;
            int u = ks * 2 + mA;
            ldsm_x4(sb + KO + (uint32_t)(n * 64 + ((u ^ ((n >> 1) & 3)) << 4)),
                    bf[p][0], bf[p][1], bf[p][2], bf[p][3]);
        }
        #pragma unroll
        for (int nt = 0; nt < 8; ++nt)
            MMA_F16(sacc[nt], a[0], a[1], a[2], a[3],
                    bf[nt >> 1][(nt & 1) * 2], bf[nt >> 1][(nt & 1) * 2 + 1]);
    }

    // ---- scale + (bias+mask fp16) + softmax (register resident) ----
    const int g = lane >> 2, t = lane & 3;
    const int l0 = w * 16 + g, l1 = l0 + 8;
    const int win = b & 63;
    const bool v0 = (l0 < L_TOK), v1 = (l1 < L_TOK);
    const int l0c = v0 ? l0 : 48, l1c = v1 ? l1 : 48;
    const __half* bm0 = bm + (((size_t)win * 16 + h) * 49 + l0c) * 56;
    const __half* bm1 = bm + (((size_t)win * 16 + h) * 49 + l1c) * 56;
    const float scale = 0.1767766952966369f;

    float mx0 = -1e30f, mx1 = -1e30f;
    #pragma unroll
    for (int j = 0; j < 8; ++j) {
        int ma = 8 * j + 2 * t;
        float* c = sacc[j];
        if (ma < L_TOK) {
            float2 ba = __half22float2(*(const __half2*)&bm0[ma]);
            float2 bb = __half22float2(*(const __half2*)&bm1[ma]);
            c[0] = v0 ? fmaf(c[0], scale, ba.x) : -1e30f;
            c[1] = (v0 && ma + 1 < L_TOK) ? fmaf(c[1], scale, ba.y) : -1e30f;
            c[2] = v1 ? fmaf(c[2], scale, bb.x) : -1e30f;
            c[3] = (v1 && ma + 1 < L_TOK) ? fmaf(c[3], scale, bb.y) : -1e30f;
        } else {
            c[0] = c[1] = c[2] = c[3] = -1e30f;
        }
        mx0 = fmaxf(mx0, fmaxf(c[0], c[1]));
        mx1 = fmaxf(mx1, fmaxf(c[2], c[3]));
    }
    mx0 = fmaxf(mx0, __shfl_xor_sync(0xffffffffu, mx0, 1));
    mx0 = fmaxf(mx0, __shfl_xor_sync(0xffffffffu, mx0, 2));
    mx1 = fmaxf(mx1, __shfl_xor_sync(0xffffffffu, mx1, 1));
    mx1 = fmaxf(mx1, __shfl_xor_sync(0xffffffffu, mx1, 2));

    float s0 = 0.f, s1 = 0.f;
    #pragma unroll
    for (int j = 0; j < 8; ++j) {
        float* c = sacc[j];
        c[0] = __expf(c[0] - mx0);
        c[1] = __expf(c[1] - mx0);
        c[2] = __expf(c[2] - mx1);
        c[3] = __expf(c[3] - mx1);
        s0 += c[0] + c[1];
        s1 += c[2] + c[3];
    }
    s0 += __shfl_xor_sync(0xffffffffu, s0, 1);
    s0 += __shfl_xor_sync(0xffffffffu, s0, 2);
    s1 += __shfl_xor_sync(0xffffffffu, s1, 1);
    s1 += __shfl_xor_sync(0xffffffffu, s1, 2);
    const float i0 = 1.f / s0, i1 = 1.f / s1;

    // ---- O = P @ V : P fed directly from QK accumulator registers ----
    float oacc[4][4];
    #pragma unroll
    for (int nt = 0; nt < 4; ++nt)
        #pragma unroll
        for (int r = 0; r < 4; ++r) oacc[nt][r] = 0.f;

    #pragma unroll
    for (int ks = 0; ks < 4; ++ks) {
        __half2 pa0 = __floats2half2_rn(sacc[2 * ks][0] * i0,     sacc[2 * ks][1] * i0);
        __half2 pa1 = __floats2half2_rn(sacc[2 * ks][2] * i1,     sacc[2 * ks][3] * i1);
        __half2 pa2 = __floats2half2_rn(sacc[2 * ks + 1][0] * i0, sacc[2 * ks + 1][1] * i0);
        __half2 pa3 = __floats2half2_rn(sacc[2 * ks + 1][2] * i1, sacc[2 * ks + 1][3] * i1);
        uint32_t a0 = *(uint32_t*)&pa0, a1 = *(uint32_t*)&pa1;
        uint32_t a2 = *(uint32_t*)&pa2, a3 = *(uint32_t*)&pa3;

        uint32_t bf[2][4];
        #pragma unroll
        for (int p = 0; p < 2; ++p) {
            int vr = ks * 16 + mA * 8 + rr;
            int u  = p * 2 + kU;
            ldsm_x4_t(sb + VO + (uint32_t)(vr * 64 + ((u ^ ((vr >> 1) & 3)) << 4)),
                      bf[p][0], bf[p][1], bf[p][2], bf[p][3]);
        }
        #pragma unroll
        for (int nt = 0; nt < 4; ++nt)
            MMA_F16(oacc[nt], a0, a1, a2, a3,
                    bf[nt >> 1][(nt & 1) * 2], bf[nt >> 1][(nt & 1) * 2 + 1]);
    }

    // ---- write merged-head output (fp16, feeds proj GEMM) ----
    __half* orow0 = att + ((size_t)b * L_TOK + l0) * C_DIM + h * HD_DIM;
    __half* orow1 = orow0 + (size_t)8 * C_DIM;
    #pragma unroll
    for (int nt = 0; nt < 4; ++nt) {
        int d = nt * 8 + t * 2;
        if (v0) *(__half2*)(orow0 + d) = __floats2half2_rn(oacc[nt][0], oacc[nt][1]);
        if (v1) *(__half2*)(orow1 + d) = __floats2half2_rn(oacc[nt][2], oacc[nt][3]);
    }
}

// ---------------------------------------------------------------------------
// kernel_launch
// ---------------------------------------------------------------------------
extern "C" void kernel_launch(void* const* d_in, const int* in_sizes, int n_in,
                              void* d_out, int out_size) {
    const float* x     = (const float*)d_in[0];
    const float* mask  = (const float*)d_in[1];
    const float* bias  = (const float*)d_in[2];
    const float* wqkv  = (const float*)d_in[3];
    const float* wproj = (const float*)d_in[4];
    float*       out   = (float*)d_out;

    void *xh, *qkvh, *atth, *wqkvth, *wprojth, *bm;
    cudaGetSymbolAddress(&xh, g_xh);
    cudaGetSymbolAddress(&qkvh, g_qkvh);
    cudaGetSymbolAddress(&atth, g_atth);
    cudaGetSymbolAddress(&wqkvth, g_wqkvth);
    cudaGetSymbolAddress(&wprojth, g_wprojth);
    cudaGetSymbolAddress(&bm, g_bm);

    cudaFuncSetAttribute(gemm_h<true>,  cudaFuncAttributeMaxDynamicSharedMemorySize, GSMEM);
    cudaFuncSetAttribute(gemm_h<false>, cudaFuncAttributeMaxDynamicSharedMemorySize, GSMEM);

    // 0) Pre-passes
    const int n4 = ROWS * C_DIM / 4;
    f32_to_f16<<<(n4 + 255) / 256, 256>>>((const float4*)x, (__half2*)xh, n4);
    transpose_h<<<dim3(1536 / 32, 512 / 32), dim3(32, 8)>>>(wqkv, (__half*)wqkvth, C_DIM, 3 * C_DIM);
    transpose_h<<<dim3(512 / 32, 512 / 32), dim3(32, 8)>>>(wproj, (__half*)wprojth, C_DIM, C_DIM);
    const int bmTot = 64 * 16 * 49 * 56;
    build_bm<<<(bmTot + 255) / 256, 256>>>(mask, bias, (__half*)bm);

    // 1) QKV projection
    gemm_h<true><<<dim3(1536 / 128, ROWS / 128), 256, GSMEM>>>(
        (const __half*)xh, (const __half*)wqkvth, qkvh, ROWS, 3 * C_DIM, C_DIM);

    // 2) Windowed attention (P register-direct, fp16 bm)
    attn_h<<<dim3(B_TOT, H_HEADS), 128>>>((const __half*)qkvh, (const __half*)bm, (__half*)atth);

    // 3) Output projection (fp32 out)
    gemm_h<false><<<dim3(C_DIM / 128, ROWS / 128), 256, GSMEM>>>(
        (const __half*)atth, (const __half*)wprojth, out, ROWS, C_DIM, C_DIM);
}

// round 16
// speedup vs baseline: 1.0531x; 1.0078x over previous
#include <cuda_runtime.h>
#include <cuda_fp16.h>
#include <math.h>
#include <stdint.h>

// ---------------------------------------------------------------------------
// Problem constants
// ---------------------------------------------------------------------------
#define B_TOT   2048
#define L_TOK   49
#define C_DIM   512
#define H_HEADS 16
#define HD_DIM  32
#define ROWS    (B_TOT * L_TOK)        // 100352 = 784 * 128

// Scratch (device globals; allocation-free per harness rules)
static __device__ unsigned short g_xh[(size_t)ROWS * C_DIM];
static __device__ unsigned short g_qkvh[(size_t)ROWS * 3 * C_DIM];
static __device__ unsigned short g_atth[(size_t)ROWS * C_DIM];
static __device__ unsigned short g_wqkvth[3 * C_DIM * C_DIM];
static __device__ unsigned short g_wprojth[C_DIM * C_DIM];
static __device__ unsigned short g_bm[64 * 16 * 49 * 56];      // fp16 bias+mask

// ---------------------------------------------------------------------------
// Helpers
// ---------------------------------------------------------------------------
__device__ __forceinline__ uint32_t smem_u32(const void* p) {
    uint32_t a;
    asm("{ .reg .u64 t; cvta.to.shared.u64 t, %1; cvt.u32.u64 %0, t; }" : "=r"(a) : "l"(p));
    return a;
}

__device__ __forceinline__ void ldsm_x4(uint32_t addr, uint32_t& r0, uint32_t& r1,
                                        uint32_t& r2, uint32_t& r3) {
    asm volatile("ldmatrix.sync.aligned.m8n8.x4.shared.b16 {%0,%1,%2,%3}, [%4];"
                 : "=r"(r0), "=r"(r1), "=r"(r2), "=r"(r3) : "r"(addr));
}

__device__ __forceinline__ void ldsm_x4_t(uint32_t addr, uint32_t& r0, uint32_t& r1,
                                          uint32_t& r2, uint32_t& r3) {
    asm volatile("ldmatrix.sync.aligned.m8n8.x4.trans.shared.b16 {%0,%1,%2,%3}, [%4];"
                 : "=r"(r0), "=r"(r1), "=r"(r2), "=r"(r3) : "r"(addr));
}

__device__ __forceinline__ void cp_async16(uint32_t d, const void* s) {
    asm volatile("cp.async.cg.shared.global [%0], [%1], 16;" :: "r"(d), "l"(s) : "memory");
}
__device__ __forceinline__ void cp_async16z(uint32_t d, const void* s, uint32_t sz) {
    asm volatile("cp.async.cg.shared.global [%0], [%1], 16, %2;"
                 :: "r"(d), "l"(s), "r"(sz) : "memory");
}
#define CP_COMMIT() asm volatile("cp.async.commit_group;" ::: "memory")

#define MMA_F16(c, a0, a1, a2, a3, b0, b1)                                      \
    asm volatile(                                                               \
        "mma.sync.aligned.m16n8k16.row.col.f32.f16.f16.f32 "                    \
        "{%0,%1,%2,%3}, {%4,%5,%6,%7}, {%8,%9}, {%0,%1,%2,%3};\n"               \
        : "+f"((c)[0]), "+f"((c)[1]), "+f"((c)[2]), "+f"((c)[3])                \
        : "r"(a0), "r"(a1), "r"(a2), "r"(a3), "r"(b0), "r"(b1))

// ---------------------------------------------------------------------------
// Unified pre-pass kernel: four independent memory-bound tasks partitioned
// by blockIdx.x so they run concurrently in one launch.
//   [0, NB_X)              : x f32 -> f16 (one float4 per thread)
//   [NB_X, +NB_WQ)         : transpose+convert w_qkv   (32x32 tiles, 48x16)
//   [.., +NB_WP)           : transpose+convert w_proj  (16x16)
//   [.., +NB_BM)           : bias+mask table (fp16)
// ---------------------------------------------------------------------------
#define NB_X   50176                    // 12,845,056 float4 / 256
#define NB_WQ  768
#define NB_WP  256
#define NB_BM  10976
#define NB_TOT (NB_X + NB_WQ + NB_WP + NB_BM)

__global__ void prepass(const float4* __restrict__ x4, __half2* __restrict__ xh2,
                        const float* __restrict__ wqkv, __half* __restrict__ wqkvt,
                        const float* __restrict__ wproj, __half* __restrict__ wprojt,
                        const float* __restrict__ mask, const float* __restrict__ bias,
                        __half* __restrict__ bm) {
    __shared__ float t[32][33];
    const int b = blockIdx.x;
    const int tid = threadIdx.x;

    if (b < NB_X) {
        int i = b * 256 + tid;
        float4 v = x4[i];
        xh2[2 * i]     = __floats2half2_rn(v.x, v.y);
        xh2[2 * i + 1] = __floats2half2_rn(v.z, v.w);
    } else if (b < NB_X + NB_WQ + NB_WP) {
        const bool isQ = (b < NB_X + NB_WQ);
        const int bi   = isQ ? (b - NB_X) : (b - NB_X - NB_WQ);
        const int ntx  = isQ ? 48 : 16;
        const float* W = isQ ? wqkv : wproj;
        __half* Wt     = isQ ? wqkvt : wprojt;
        const int Ndim = isQ ? 1536 : 512;
        const int n0 = (bi % ntx) * 32, k0 = (bi / ntx) * 32;
        const int x = tid & 31, y = tid >> 5;
        #pragma unroll
        for (int i = 0; i < 32; i += 8)
            t[y + i][x] = W[(size_t)(k0 + y + i) * Ndim + n0 + x];
        __syncthreads();
        #pragma unroll
        for (int i = 0; i < 32; i += 8)
            Wt[(size_t)(n0 + y + i) * C_DIM + k0 + x] = __float2half_rn(t[x][y + i]);
    } else {
        int idx = (b - NB_X - NB_WQ - NB_WP) * 256 + tid;
        const int TOT = 64 * 16 * 49 * 56;
        if (idx >= TOT) return;
        int m = idx % 56;
        int r = idx / 56;
        int l = r % 49;
        int wh = r / 49;
        int h = wh % 16;
        int win = wh / 16;
        float v = 0.f;
        if (m < 49) {
            int lh = l / 7, lw = l - lh * 7;
            int mh = m / 7, mw = m - mh * 7;
            int ri = (lh - mh + 6) * 13 + (lw - mw + 6);
            v = bias[ri * 16 + h] + mask[(win * 49 + l) * 49 + m];
        }
        bm[idx] = __float2half_rn(v);
    }
}

// ---------------------------------------------------------------------------
// fp16 GEMM (R12-proven): C[M,N] = A[M,K] * Bt[N,K]^T, fp32 accumulate.
// BM=BN=128, BK=64 halves (128B rows), 3 stages x 32 KB dynamic smem,
// 256 threads (8 warps, 2m x 4n), warp tile 64x32, mma.m16n8k16.
// SW128 swizzle u ^ (row & 7); single barrier per k-tile.
// ---------------------------------------------------------------------------
#define GSTG_B 32768
#define GB_HALF 16384
#define GSMEM (3 * GSTG_B)

template <bool OUT_HALF>
__global__ __launch_bounds__(256, 2)
void gemm_h(const __half* __restrict__ A, const __half* __restrict__ Bt,
            void* __restrict__ Cv, int M, int N, int K) {
    extern __shared__ __align__(16) char dsm[];

    const int tid = threadIdx.x, lane = tid & 31, warp = tid >> 5;
    const int wm = warp >> 2, wn = warp & 3;
    const int m0 = blockIdx.y * 128, n0 = blockIdx.x * 128;

    const int r_ld = tid >> 1;
    const int cb   = (tid & 1) * 4;
    const __half* ag = A  + (size_t)(m0 + r_ld) * K + cb * 8;
    const __half* bg = Bt + (size_t)(n0 + r_ld) * K + cb * 8;
    uint32_t adst[4], bdst[4];
    #pragma unroll
    for (int j = 0; j < 4; ++j) {
        adst[j] = (uint32_t)(r_ld * 128 + (((cb + j) ^ (r_ld & 7)) << 4));
        bdst[j] = GB_HALF + adst[j];
    }

    uint32_t sb[3];
    #pragma unroll
    for (int s = 0; s < 3; ++s) sb[s] = smem_u32(dsm) + s * GSTG_B;

    const int rr = lane & 7;
    const int mA = (lane >> 3) & 1;
    const int kU = lane >> 4;

    float acc[16][4];
    #pragma unroll
    for (int i = 0; i < 16; ++i)
        #pragma unroll
        for (int j = 0; j < 4; ++j) acc[i][j] = 0.f;

    const int nK = K >> 6;

    #pragma unroll
    for (int p = 0; p < 2; ++p) {
        #pragma unroll
        for (int j = 0; j < 4; ++j) {
            cp_async16(sb[p] + adst[j], ag + p * 64 + j * 8);
            cp_async16(sb[p] + bdst[j], bg + p * 64 + j * 8);
        }
        CP_COMMIT();
    }

    for (int kt = 0; kt < nK; ++kt) {
        if (kt + 1 < nK) asm volatile("cp.async.wait_group 1;" ::: "memory");
        else             asm volatile("cp.async.wait_group 0;" ::: "memory");
        __syncthreads();

        if (kt + 2 < nK) {
            uint32_t so = sb[(kt + 2) % 3];
            #pragma unroll
            for (int j = 0; j < 4; ++j) {
                cp_async16(so + adst[j], ag + (kt + 2) * 64 + j * 8);
                cp_async16(so + bdst[j], bg + (kt + 2) * 64 + j * 8);
            }
            CP_COMMIT();
        }

        const uint32_t aB = sb[kt % 3];
        const uint32_t bB = aB + GB_HALF;

        #pragma unroll
        for (int ks = 0; ks < 4; ++ks) {
            uint32_t af[4][4];
            #pragma unroll
            for (int mt = 0; mt < 4; ++mt) {
                int r = wm * 64 + mt * 16 + mA * 8 + rr;
                int u = ks * 2 + kU;
                ldsm_x4(aB + (uint32_t)(r * 128 + ((u ^ (r & 7)) << 4)),
                        af[mt][0], af[mt][1], af[mt][2], af[mt][3]);
            }
            uint32_t bf[2][4];
            #pragma unroll
            for (int p = 0; p < 2; ++p) {
                int n = wn * 32 + p * 16 + kU * 8 + rr;
                int u = ks * 2 + mA;
                ldsm_x4(bB + (uint32_t)(n * 128 + ((u ^ (n & 7)) << 4)),
                        bf[p][0], bf[p][1], bf[p][2], bf[p][3]);
            }
            #pragma unroll
            for (int mt = 0; mt < 4; ++mt)
                #pragma unroll
                for (int nt = 0; nt < 4; ++nt)
                    MMA_F16(acc[mt * 4 + nt],
                            af[mt][0], af[mt][1], af[mt][2], af[mt][3],
                            bf[nt >> 1][(nt & 1) * 2], bf[nt >> 1][(nt & 1) * 2 + 1]);
        }
    }

    const int g = lane >> 2, t = lane & 3;
    #pragma unroll
    for (int mt = 0; mt < 4; ++mt) {
        #pragma unroll
        for (int nt = 0; nt < 4; ++nt) {
            const float* c = acc[mt * 4 + nt];
            int r = m0 + wm * 64 + mt * 16 + g;
            int cc = n0 + wn * 32 + nt * 8 + t * 2;
            if (OUT_HALF) {
                __half* C = (__half*)Cv;
                *(__half2*)&C[(size_t)r * N + cc]       = __floats2half2_rn(c[0], c[1]);
                *(__half2*)&C[(size_t)(r + 8) * N + cc] = __floats2half2_rn(c[2], c[3]);
            } else {
                float* C = (float*)Cv;
                *(float2*)&C[(size_t)r * N + cc]       = make_float2(c[0], c[1]);
                *(float2*)&C[(size_t)(r + 8) * N + cc] = make_float2(c[2], c[3]);
            }
        }
    }
}

// ---------------------------------------------------------------------------
// fp16 tensor-core attention (R14 register-direct P, R15 fp16 bm).
// NEW (R16): V committed as a separate cp.async group; QK starts as soon as
// Q+K land, V arrival hidden under QK+softmax.
// Smem: Q [64][64B] @0, K @4096, V [64][64B] @8192 (row-major). 12.3 KB.
// ---------------------------------------------------------------------------
#define QO 0
#define KO 4096
#define VO 8192
#define ATT_SMEM 12288

__global__ __launch_bounds__(128, 6)
void attn_h(const __half* __restrict__ qkv, const __half* __restrict__ bm,
            __half* __restrict__ att) {
    __shared__ __align__(16) char smc[ATT_SMEM];
    const uint32_t sb = smem_u32(smc);

    const int b = blockIdx.x, h = blockIdx.y;
    const int tid = threadIdx.x, lane = tid & 31, w = tid >> 5;

    const __half* base = qkv + (size_t)b * L_TOK * 1536 + h * HD_DIM;

    // Group 0: Q + K
    #pragma unroll
    for (int j = 0; j < 2; ++j) {
        int u = tid * 2 + j;
        int r = u >> 2, c = u & 3;
        uint32_t sz = (r < L_TOK) ? 16u : 0u;
        const __half* src = (r < L_TOK) ? (base + (size_t)r * 1536 + c * 8) : base;
        uint32_t dst = (uint32_t)(r * 64 + ((c ^ ((r >> 1) & 3)) << 4));
        cp_async16z(sb + QO + dst, src, sz);
        cp_async16z(sb + KO + dst, src + 512, sz);
    }
    CP_COMMIT();
    // Group 1: V
    #pragma unroll
    for (int j = 0; j < 2; ++j) {
        int u = tid * 2 + j;
        int r = u >> 2, c = u & 3;
        uint32_t sz = (r < L_TOK) ? 16u : 0u;
        const __half* src = (r < L_TOK) ? (base + (size_t)r * 1536 + 1024 + c * 8) : base;
        uint32_t dst = (uint32_t)(r * 64 + ((c ^ ((r >> 1) & 3)) << 4));
        cp_async16z(sb + VO + dst, src, sz);
    }
    CP_COMMIT();

    asm volatile("cp.async.wait_group 1;" ::: "memory");   // Q, K ready
    __syncthreads();

    const int rr = lane & 7;
    const int mA = (lane >> 3) & 1;
    const int kU = lane >> 4;

    // ---- QK^T: warp w -> rows w*16..+16, cols 0..63 ----
    float sacc[8][4];
    #pragma unroll
    for (int j = 0; j < 8; ++j)
        #pragma unroll
        for (int r = 0; r < 4; ++r) sacc[j][r] = 0.f;

    #pragma unroll
    for (int ks = 0; ks < 2; ++ks) {
        uint32_t a[4];
        {
            int r = w * 16 + mA * 8 + rr;
            int u = ks * 2 + kU;
            ldsm_x4(sb + QO + (uint32_t)(r * 64 + ((u ^ ((r >> 1) & 3)) << 4)),
                    a[0], a[1], a[2], a[3]);
        }
        uint32_t bf[4][4];
        #pragma unroll
        for (int p = 0; p < 4; ++p) {
            int n = p * 16 + kU * 8 + rr;
            int u = ks * 2 + mA;
            ldsm_x4(sb + KO + (uint32_t)(n * 64 + ((u ^ ((n >> 1) & 3)) << 4)),
                    bf[p][0], bf[p][1], bf[p][2], bf[p][3]);
        }
        #pragma unroll
        for (int nt = 0; nt < 8; ++nt)
            MMA_F16(sacc[nt], a[0], a[1], a[2], a[3],
                    bf[nt >> 1][(nt & 1) * 2], bf[nt >> 1][(nt & 1) * 2 + 1]);
    }

    // ---- scale + (bias+mask fp16) + softmax (register resident) ----
    const int g = lane >> 2, t = lane & 3;
    const int l0 = w * 16 + g, l1 = l0 + 8;
    const int win = b & 63;
    const bool v0 = (l0 < L_TOK), v1 = (l1 < L_TOK);
    const int l0c = v0 ? l0 : 48, l1c = v1 ? l1 : 48;
    const __half* bm0 = bm + (((size_t)win * 16 + h) * 49 + l0c) * 56;
    const __half* bm1 = bm + (((size_t)win * 16 + h) * 49 + l1c) * 56;
    const float scale = 0.1767766952966369f;

    float mx0 = -1e30f, mx1 = -1e30f;
    #pragma unroll
    for (int j = 0; j < 8; ++j) {
        int ma = 8 * j + 2 * t;
        float* c = sacc[j];
        if (ma < L_TOK) {
            float2 ba = __half22float2(*(const __half2*)&bm0[ma]);
            float2 bb = __half22float2(*(const __half2*)&bm1[ma]);
            c[0] = v0 ? fmaf(c[0], scale, ba.x) : -1e30f;
            c[1] = (v0 && ma + 1 < L_TOK) ? fmaf(c[1], scale, ba.y) : -1e30f;
            c[2] = v1 ? fmaf(c[2], scale, bb.x) : -1e30f;
            c[3] = (v1 && ma + 1 < L_TOK) ? fmaf(c[3], scale, bb.y) : -1e30f;
        } else {
            c[0] = c[1] = c[2] = c[3] = -1e30f;
        }
        mx0 = fmaxf(mx0, fmaxf(c[0], c[1]));
        mx1 = fmaxf(mx1, fmaxf(c[2], c[3]));
    }
    mx0 = fmaxf(mx0, __shfl_xor_sync(0xffffffffu, mx0, 1));
    mx0 = fmaxf(mx0, __shfl_xor_sync(0xffffffffu, mx0, 2));
    mx1 = fmaxf(mx1, __shfl_xor_sync(0xffffffffu, mx1, 1));
    mx1 = fmaxf(mx1, __shfl_xor_sync(0xffffffffu, mx1, 2));

    float s0 = 0.f, s1 = 0.f;
    #pragma unroll
    for (int j = 0; j < 8; ++j) {
        float* c = sacc[j];
        c[0] = __expf(c[0] - mx0);
        c[1] = __expf(c[1] - mx0);
        c[2] = __expf(c[2] - mx1);
        c[3] = __expf(c[3] - mx1);
        s0 += c[0] + c[1];
        s1 += c[2] + c[3];
    }
    s0 += __shfl_xor_sync(0xffffffffu, s0, 1);
    s0 += __shfl_xor_sync(0xffffffffu, s0, 2);
    s1 += __shfl_xor_sync(0xffffffffu, s1, 1);
    s1 += __shfl_xor_sync(0xffffffffu, s1, 2);
    const float i0 = 1.f / s0, i1 = 1.f / s1;

    // V must be resident + visible to all threads before PV ldsm
    asm volatile("cp.async.wait_group 0;" ::: "memory");
    __syncthreads();

    // ---- O = P @ V : P fed directly from QK accumulator registers ----
    float oacc[4][4];
    #pragma unroll
    for (int nt = 0; nt < 4; ++nt)
        #pragma unroll
        for (int r = 0; r < 4; ++r) oacc[nt][r] = 0.f;

    #pragma unroll
    for (int ks = 0; ks < 4; ++ks) {
        __half2 pa0 = __floats2half2_rn(sacc[2 * ks][0] * i0,     sacc[2 * ks][1] * i0);
        __half2 pa1 = __floats2half2_rn(sacc[2 * ks][2] * i1,     sacc[2 * ks][3] * i1);
        __half2 pa2 = __floats2half2_rn(sacc[2 * ks + 1][0] * i0, sacc[2 * ks + 1][1] * i0);
        __half2 pa3 = __floats2half2_rn(sacc[2 * ks + 1][2] * i1, sacc[2 * ks + 1][3] * i1);
        uint32_t a0 = *(uint32_t*)&pa0, a1 = *(uint32_t*)&pa1;
        uint32_t a2 = *(uint32_t*)&pa2, a3 = *(uint32_t*)&pa3;

        uint32_t bf[2][4];
        #pragma unroll
        for (int p = 0; p < 2; ++p) {
            int vr = ks * 16 + mA * 8 + rr;
            int u  = p * 2 + kU;
            ldsm_x4_t(sb + VO + (uint32_t)(vr * 64 + ((u ^ ((vr >> 1) & 3)) << 4)),
                      bf[p][0], bf[p][1], bf[p][2], bf[p][3]);
        }
        #pragma unroll
        for (int nt = 0; nt < 4; ++nt)
            MMA_F16(oacc[nt], a0, a1, a2, a3,
                    bf[nt >> 1][(nt & 1) * 2], bf[nt >> 1][(nt & 1) * 2 + 1]);
    }

    // ---- write merged-head output (fp16, feeds proj GEMM) ----
    __half* orow0 = att + ((size_t)b * L_TOK + l0) * C_DIM + h * HD_DIM;
    __half* orow1 = orow0 + (size_t)8 * C_DIM;
    #pragma unroll
    for (int nt = 0; nt < 4; ++nt) {
        int d = nt * 8 + t * 2;
        if (v0) *(__half2*)(orow0 + d) = __floats2half2_rn(oacc[nt][0], oacc[nt][1]);
        if (v1) *(__half2*)(orow1 + d) = __floats2half2_rn(oacc[nt][2], oacc[nt][3]);
    }
}

// ---------------------------------------------------------------------------
// kernel_launch
// ---------------------------------------------------------------------------
extern "C" void kernel_launch(void* const* d_in, const int* in_sizes, int n_in,
                              void* d_out, int out_size) {
    const float* x     = (const float*)d_in[0];
    const float* mask  = (const float*)d_in[1];
    const float* bias  = (const float*)d_in[2];
    const float* wqkv  = (const float*)d_in[3];
    const float* wproj = (const float*)d_in[4];
    float*       out   = (float*)d_out;

    void *xh, *qkvh, *atth, *wqkvth, *wprojth, *bm;
    cudaGetSymbolAddress(&xh, g_xh);
    cudaGetSymbolAddress(&qkvh, g_qkvh);
    cudaGetSymbolAddress(&atth, g_atth);
    cudaGetSymbolAddress(&wqkvth, g_wqkvth);
    cudaGetSymbolAddress(&wprojth, g_wprojth);
    cudaGetSymbolAddress(&bm, g_bm);

    cudaFuncSetAttribute(gemm_h<true>,  cudaFuncAttributeMaxDynamicSharedMemorySize, GSMEM);
    cudaFuncSetAttribute(gemm_h<false>, cudaFuncAttributeMaxDynamicSharedMemorySize, GSMEM);

    // 0) Unified pre-pass (x conv + both weight transposes + bm table)
    prepass<<<NB_TOT, 256>>>((const float4*)x, (__half2*)xh,
                             wqkv, (__half*)wqkvth,
                             wproj, (__half*)wprojth,
                             mask, bias, (__half*)bm);

    // 1) QKV projection
    gemm_h<true><<<dim3(1536 / 128, ROWS / 128), 256, GSMEM>>>(
        (const __half*)xh, (const __half*)wqkvth, qkvh, ROWS, 3 * C_DIM, C_DIM);

    // 2) Windowed attention (register-direct P, fp16 bm, split V wait)
    attn_h<<<dim3(B_TOT, H_HEADS), 128>>>((const __half*)qkvh, (const __half*)bm, (__half*)atth);

    // 3) Output projection (fp32 out)
    gemm_h<false><<<dim3(C_DIM / 128, ROWS / 128), 256, GSMEM>>>(
        (const __half*)atth, (const __half*)wprojth, out, ROWS, C_DIM, C_DIM);
}